// round 4
// baseline (speedup 1.0000x reference)
#include <cuda_runtime.h>
#include <math.h>

// Problem constants
#define BB 32        // batch
#define CC 128       // FEAT_DIM
#define NPIX 4096    // H*W
#define SD 256       // SLOT_DIM
#define NS 8         // N_SLOTS
#define NH 4         // N_HEADS
#define HD 64        // HEAD_DIM
#define NJ 32        // NH*NS  (j = h*8 + s)
#define TILE_N 128
#define NROWS 256    // BB*NS flattened rows
#define FST 132      // featT smem row stride (padded floats)
#define AST 132      // attn smem row stride
#define RS (NROWS * SD)

// Scratch (device globals; no allocation allowed)
__device__ float gA[BB * CC * NJ];      // per-batch folded K-projection (128x32)
__device__ float gSbias[BB * NJ];       // score bias from bk
__device__ float gM[BB * NJ * CC];      // M[b][j][c]
__device__ float gSsum[BB * NJ];        // sum_n attn[b][j]
__device__ float gAgg[RS];              // agg (GRU input x), [row][dim]
__device__ float gUpd[RS];              // GRU output (updated slots)
__device__ float gLN[RS];               // post-LN of updated
__device__ float gHid[NROWS * 2 * SD];  // MLP hidden (post-ReLU)
__device__ float gPart[6 * RS];         // gRZ[256][512] | gIN[256][256] | gHN[256][256]

#define gRZ (gPart)
#define gIN (gPart + NROWS * 512)
#define gHN (gPart + NROWS * 512 + NROWS * 256)

// ---- f32x2 packed helpers -------------------------------------------------
__device__ __forceinline__ unsigned long long pack2(float x, float y) {
    unsigned long long r;
    asm("mov.b64 %0, {%1, %2};" : "=l"(r) : "f"(x), "f"(y));
    return r;
}
__device__ __forceinline__ float2 unpack2(unsigned long long p) {
    float2 f;
    asm("mov.b64 {%0, %1}, %2;" : "=f"(f.x), "=f"(f.y) : "l"(p));
    return f;
}
__device__ __forceinline__ void ffma2(unsigned long long& d,
                                      unsigned long long a, unsigned long long b) {
    asm("fma.rn.f32x2 %0, %1, %2, %0;" : "+l"(d) : "l"(a), "l"(b));
}

// ---------------------------------------------------------------------------
// Kernel 1: LN(slots) -> q(half) -> A fold for a head-pair. grid = BB*2 = 64.
// Also zeros gM, gSsum, gRZ.
// ---------------------------------------------------------------------------
__global__ void __launch_bounds__(256) prep_kernel(
    const float* __restrict__ slots,
    const float* __restrict__ Wq, const float* __restrict__ bq,
    const float* __restrict__ Wk, const float* __restrict__ bk,
    const float* __restrict__ g_pre, const float* __restrict__ b_pre)
{
    __shared__ float ln_s[NS][SD];
    __shared__ float qp[NS][128];
    __shared__ float q_s[NS][128];
    int b = blockIdx.x >> 1, hp = blockIdx.x & 1;
    int t = threadIdx.x;
    int w = t >> 5, lane = t & 31;

    for (int i = t; i < 16 * CC; i += 256)
        gM[b * NJ * CC + hp * 16 * CC + i] = 0.f;
    if (t < 16) gSsum[b * NJ + hp * 16 + t] = 0.f;
    // zero gRZ slice (131072 floats / 64 blocks = 2048)
    {
        float* z = gRZ + (size_t)blockIdx.x * 2048;
        for (int i = t; i < 2048; i += 256) z[i] = 0.f;
    }

    {
        const float* row = slots + (size_t)(b * NS + w) * SD;
        float s1 = 0.f, s2 = 0.f;
        for (int k = lane; k < SD; k += 32) { float v = row[k]; s1 += v; s2 += v * v; }
        #pragma unroll
        for (int o = 16; o; o >>= 1) {
            s1 += __shfl_xor_sync(0xffffffffu, s1, o);
            s2 += __shfl_xor_sync(0xffffffffu, s2, o);
        }
        float mu = s1 * (1.f / SD);
        float var = s2 * (1.f / SD) - mu * mu;
        float rs = rsqrtf(var + 1e-5f);
        for (int k = lane; k < SD; k += 32)
            ln_s[w][k] = (row[k] - mu) * rs * g_pre[k] + b_pre[k];
    }
    __syncthreads();

    {
        int dimL = t & 127, ks = t >> 7;
        int dim = hp * 128 + dimL;
        float acc[NS];
        #pragma unroll
        for (int s = 0; s < NS; s++) acc[s] = 0.f;
        int kb = ks * 128;
        #pragma unroll 8
        for (int k = kb; k < kb + 128; k++) {
            float wv = Wq[k * SD + dim];
            #pragma unroll
            for (int s = 0; s < NS; s++) acc[s] += ln_s[s][k] * wv;
        }
        if (ks == 1) {
            #pragma unroll
            for (int s = 0; s < NS; s++) qp[s][dimL] = acc[s];
        }
        __syncthreads();
        if (ks == 0) {
            float bqv = bq[dim];
            #pragma unroll
            for (int s = 0; s < NS; s++) q_s[s][dimL] = acc[s] + qp[s][dimL] + bqv;
        }
    }
    __syncthreads();

    const float scale = 0.125f;
    for (int idx = t; idx < CC * 16; idx += 256) {
        int c = idx >> 4, jl = idx & 15;
        int hl = jl >> 3, s = jl & 7;
        const float* wk = Wk + (size_t)c * SD + (2 * hp + hl) * HD;
        const float* qq = &q_s[s][hl * HD];
        float acc = 0.f;
        #pragma unroll 8
        for (int d = 0; d < HD; d++) acc += wk[d] * qq[d];
        gA[b * CC * NJ + c * NJ + hp * 16 + jl] = acc * scale;
    }
    if (t < 16) {
        int jl = t, hl = jl >> 3, s = jl & 7;
        float acc = 0.f;
        for (int d = 0; d < HD; d++)
            acc += bk[(2 * hp + hl) * HD + d] * q_s[s][hl * HD + d];
        gSbias[b * NJ + hp * 16 + jl] = acc * scale;
    }
}

// ---------------------------------------------------------------------------
// Kernel 2 (heavy): scores + fused softmax + M partials, f32x2. grid (32, 32).
// ---------------------------------------------------------------------------
__global__ void __launch_bounds__(256) main_kernel(const float* __restrict__ features)
{
    extern __shared__ float sm[];
    float* featT = sm;                                       // [CC][FST]
    unsigned long long* A2 = (unsigned long long*)(featT + CC * FST); // [CC][NJ] dup pairs
    float* attn = (float*)(A2 + CC * NJ);                    // [NJ][AST]

    int tile = blockIdx.x, b = blockIdx.y;
    int t = threadIdx.x;
    int n0 = tile * TILE_N;

    const float* fb = features + (size_t)b * CC * NPIX + n0;
    for (int i = t; i < CC * TILE_N / 4; i += 256) {
        int c = i >> 5, n4 = i & 31;
        ((float4*)(featT + c * FST))[n4] = ((const float4*)(fb + (size_t)c * NPIX))[n4];
    }
    for (int i = t; i < CC * NJ; i += 256) {
        float v = gA[b * CC * NJ + i];
        A2[i] = pack2(v, v);
    }
    __syncthreads();

    // Phase 1: scores (f32x2, pair over n) + bias + fused softmax
    {
        int jg = t & 7, ng = t >> 3;
        int nb = ng * 4, jb = jg * 4;
        unsigned long long acc2[2][4];
        #pragma unroll
        for (int i2 = 0; i2 < 2; i2++)
            #pragma unroll
            for (int u = 0; u < 4; u++) acc2[i2][u] = 0ull;

        #pragma unroll 4
        for (int c = 0; c < CC; c++) {
            ulonglong2 ft = *(const ulonglong2*)&featT[c * FST + nb];    // (n0n1),(n2n3)
            ulonglong2 aLo = *(const ulonglong2*)&A2[c * NJ + jb];       // dup j0, j1
            ulonglong2 aHi = *(const ulonglong2*)&A2[c * NJ + jb + 2];   // dup j2, j3
            ffma2(acc2[0][0], ft.x, aLo.x); ffma2(acc2[0][1], ft.x, aLo.y);
            ffma2(acc2[0][2], ft.x, aHi.x); ffma2(acc2[0][3], ft.x, aHi.y);
            ffma2(acc2[1][0], ft.y, aLo.x); ffma2(acc2[1][1], ft.y, aLo.y);
            ffma2(acc2[1][2], ft.y, aHi.x); ffma2(acc2[1][3], ft.y, aHi.y);
        }

        float acc[4][4];
        #pragma unroll
        for (int i2 = 0; i2 < 2; i2++)
            #pragma unroll
            for (int u = 0; u < 4; u++) {
                float2 p = unpack2(acc2[i2][u]);
                acc[2 * i2 + 0][u] = p.x;
                acc[2 * i2 + 1][u] = p.y;
            }

        float sbv[4];
        #pragma unroll
        for (int u = 0; u < 4; u++) sbv[u] = gSbias[b * NJ + jb + u];
        #pragma unroll
        for (int i = 0; i < 4; i++)
            #pragma unroll
            for (int u = 0; u < 4; u++) acc[i][u] += sbv[u];

        // softmax over 8 slots of a head (partner lane t^1 holds the other 4)
        #pragma unroll
        for (int i = 0; i < 4; i++) {
            float m = fmaxf(fmaxf(acc[i][0], acc[i][1]), fmaxf(acc[i][2], acc[i][3]));
            m = fmaxf(m, __shfl_xor_sync(0xffffffffu, m, 1));
            float s = 0.f;
            #pragma unroll
            for (int u = 0; u < 4; u++) { acc[i][u] = __expf(acc[i][u] - m); s += acc[i][u]; }
            s += __shfl_xor_sync(0xffffffffu, s, 1);
            float inv = 1.f / s;
            #pragma unroll
            for (int u = 0; u < 4; u++) acc[i][u] *= inv;
        }

        #pragma unroll
        for (int u = 0; u < 4; u++) {
            float4 v = make_float4(acc[0][u], acc[1][u], acc[2][u], acc[3][u]);
            *(float4*)&attn[(jb + u) * AST + nb] = v;
        }

        float p[4];
        #pragma unroll
        for (int u = 0; u < 4; u++)
            p[u] = acc[0][u] + acc[1][u] + acc[2][u] + acc[3][u];
        #pragma unroll
        for (int u = 0; u < 4; u++) {
            p[u] += __shfl_xor_sync(0xffffffffu, p[u], 8);
            p[u] += __shfl_xor_sync(0xffffffffu, p[u], 16);
        }
        if ((t & 31) < 8) {
            #pragma unroll
            for (int u = 0; u < 4; u++) atomicAdd(&gSsum[b * NJ + jb + u], p[u]);
        }
    }
    __syncthreads();

    // Phase 3: M[j][c] partials (f32x2, pair over reduced n)
    {
        int jb = (t >> 5) * 4, cg = t & 31;
        unsigned long long acc2[4][4];
        #pragma unroll
        for (int u = 0; u < 4; u++)
            #pragma unroll
            for (int r = 0; r < 4; r++) acc2[u][r] = 0ull;

        for (int nn = 0; nn < TILE_N; nn += 4) {
            ulonglong2 av[4];
            #pragma unroll
            for (int u = 0; u < 4; u++)
                av[u] = *(const ulonglong2*)&attn[(jb + u) * AST + nn];
            #pragma unroll
            for (int r = 0; r < 4; r++) {
                ulonglong2 fv = *(const ulonglong2*)&featT[(cg + 32 * r) * FST + nn];
                #pragma unroll
                for (int u = 0; u < 4; u++) {
                    ffma2(acc2[u][r], av[u].x, fv.x);
                    ffma2(acc2[u][r], av[u].y, fv.y);
                }
            }
        }
        float* gm = gM + b * NJ * CC;
        #pragma unroll
        for (int u = 0; u < 4; u++)
            #pragma unroll
            for (int r = 0; r < 4; r++) {
                float2 pr = unpack2(acc2[u][r]);
                atomicAdd(&gm[(jb + u) * CC + cg + 32 * r], pr.x + pr.y);
            }
    }
}

// ---------------------------------------------------------------------------
// Kernel 3: agg[row][dim] = M[b][j] @ Wv[:,dim] + Ssum*bv. Block per (b, head).
// ---------------------------------------------------------------------------
__global__ void __launch_bounds__(256) agg_kernel(
    const float* __restrict__ Wv, const float* __restrict__ bv)
{
    __shared__ float Ms[NS][CC];
    __shared__ float Wvs[CC][HD];
    int b = blockIdx.x >> 2, h = blockIdx.x & 3;
    int t = threadIdx.x;
    {
        int s = t >> 5, c4 = t & 31;
        ((float4*)&Ms[s][0])[c4] =
            ((const float4*)(gM + (size_t)b * NJ * CC + (h * 8 + s) * CC))[c4];
    }
    #pragma unroll
    for (int j = 0; j < 8; j++) {
        int i = t + j * 256;
        int c = i >> 4, d4 = i & 15;
        ((float4*)&Wvs[c][0])[d4] =
            ((const float4*)(Wv + (size_t)c * SD + h * HD))[d4];
    }
    __syncthreads();
    #pragma unroll
    for (int rep = 0; rep < 2; rep++) {
        int o = t + rep * 256;
        int s = o >> 6, d = o & 63;
        int j = h * 8 + s;
        float acc = gSsum[b * NJ + j] * bv[h * HD + d];
        #pragma unroll 8
        for (int c = 0; c < CC; c++) acc += Ms[s][c] * Wvs[c][d];
        gAgg[(size_t)(b * NS + s) * SD + h * HD + d] = acc;
    }
}

// ---------------------------------------------------------------------------
// Kernel 4: unified GRU gate GEMM, f32x2. grid (8 m, 12 nt, 2 phase).
// r/z gate cols: atomicAdd into zero-primed gRZ (sums ih+hh contributions).
// n-gate cols: store i_n (phase 0) / h_n (phase 1).
// B operand W[768][256] is n-major (k contiguous).
// ---------------------------------------------------------------------------
__global__ void __launch_bounds__(256) gru_kernel(
    const float* __restrict__ slots,
    const float* __restrict__ W_ih, const float* __restrict__ W_hh)
{
    __shared__ unsigned long long As2[16][32];   // [k2][m]
    __shared__ unsigned long long Bs2[16][64];   // [k2][n]
    int m0 = blockIdx.x * 32;
    int nt = blockIdx.y;
    int phase = blockIdx.z;
    int nrow0 = nt * 64;
    int t = threadIdx.x;
    int mi = t >> 4, ni = t & 15;

    const float* A = phase ? slots : gAgg;
    const float* W = phase ? W_hh : W_ih;

    unsigned long long acc2[2][4];
    #pragma unroll
    for (int i = 0; i < 2; i++)
        #pragma unroll
        for (int j = 0; j < 4; j++) acc2[i][j] = 0ull;

    for (int kk = 0; kk < SD; kk += 32) {
        {   // stage A: 32m x 32k
            int row = t >> 3, q = t & 7;
            float4 v = *(const float4*)(A + (size_t)(m0 + row) * SD + kk + q * 4);
            As2[2 * q + 0][row] = pack2(v.x, v.y);
            As2[2 * q + 1][row] = pack2(v.z, v.w);
        }
        #pragma unroll
        for (int rep = 0; rep < 2; rep++) {   // stage B: 64n x 32k
            int idx = t + rep * 256;
            int row = idx >> 3, q = idx & 7;
            float4 v = *(const float4*)(W + (size_t)(nrow0 + row) * SD + kk + q * 4);
            Bs2[2 * q + 0][row] = pack2(v.x, v.y);
            Bs2[2 * q + 1][row] = pack2(v.z, v.w);
        }
        __syncthreads();
        #pragma unroll
        for (int k2 = 0; k2 < 16; k2++) {
            ulonglong2 a2 = *(const ulonglong2*)&As2[k2][mi * 2];
            ulonglong2 b2a = *(const ulonglong2*)&Bs2[k2][ni * 4];
            ulonglong2 b2b = *(const ulonglong2*)&Bs2[k2][ni * 4 + 2];
            ffma2(acc2[0][0], a2.x, b2a.x); ffma2(acc2[0][1], a2.x, b2a.y);
            ffma2(acc2[0][2], a2.x, b2b.x); ffma2(acc2[0][3], a2.x, b2b.y);
            ffma2(acc2[1][0], a2.y, b2a.x); ffma2(acc2[1][1], a2.y, b2a.y);
            ffma2(acc2[1][2], a2.y, b2b.x); ffma2(acc2[1][3], a2.y, b2b.y);
        }
        __syncthreads();
    }

    #pragma unroll
    for (int i = 0; i < 2; i++) {
        int m = m0 + mi * 2 + i;
        #pragma unroll
        for (int j = 0; j < 4; j++) {
            float2 pr = unpack2(acc2[i][j]);
            float c = pr.x + pr.y;
            int col = nrow0 + ni * 4 + j;
            if (col < 512) {
                atomicAdd(&gRZ[(size_t)m * 512 + col], c);
            } else {
                float* dst = phase ? gHN : gIN;
                dst[(size_t)m * SD + (col - 512)] = c;
            }
        }
    }
}

// ---------------------------------------------------------------------------
// Kernel 5: GRU nonlin + post-LN + prime out = upd + b2. grid 32, warp/row.
// ---------------------------------------------------------------------------
__global__ void __launch_bounds__(256) fin_kernel(
    const float* __restrict__ slots,
    const float* __restrict__ b_ih, const float* __restrict__ b_hh,
    const float* __restrict__ g_post, const float* __restrict__ b_post,
    const float* __restrict__ b2, float* __restrict__ out)
{
    int row = blockIdx.x * 8 + (threadIdx.x >> 5);
    int lane = threadIdx.x & 31;
    float vals[8];
    float s1 = 0.f, s2 = 0.f;
    size_t ro = (size_t)row * SD;
    #pragma unroll
    for (int r8 = 0; r8 < 8; r8++) {
        int d = r8 * 32 + lane;
        float rz_r = gRZ[(size_t)row * 512 + d] + b_ih[d] + b_hh[d];
        float rz_z = gRZ[(size_t)row * 512 + 256 + d] + b_ih[SD + d] + b_hh[SD + d];
        float in_ = gIN[ro + d] + b_ih[2 * SD + d];
        float hn = gHN[ro + d] + b_hh[2 * SD + d];
        float r = 1.f / (1.f + expf(-rz_r));
        float z = 1.f / (1.f + expf(-rz_z));
        float nn = tanhf(in_ + r * hn);
        float hp = slots[ro + d];
        float v = (1.f - z) * nn + z * hp;
        gUpd[ro + d] = v;
        out[ro + d] = v + b2[d];
        vals[r8] = v;
        s1 += v; s2 += v * v;
    }
    #pragma unroll
    for (int o = 16; o; o >>= 1) {
        s1 += __shfl_xor_sync(0xffffffffu, s1, o);
        s2 += __shfl_xor_sync(0xffffffffu, s2, o);
    }
    float mu = s1 * (1.f / SD);
    float var = s2 * (1.f / SD) - mu * mu;
    float rs = rsqrtf(var + 1e-5f);
    #pragma unroll
    for (int r8 = 0; r8 < 8; r8++) {
        int d = r8 * 32 + lane;
        gLN[ro + d] = (vals[r8] - mu) * rs * g_post[d] + b_post[d];
    }
}

// ---------------------------------------------------------------------------
// Kernel 6: gHid = relu(gLN @ W1 + b1), f32x2. W1 [256][512] k-major.
// grid (8 m, 8 n). Tile 32x64.
// ---------------------------------------------------------------------------
__global__ void __launch_bounds__(256) mlp1_kernel(
    const float* __restrict__ W1, const float* __restrict__ b1)
{
    __shared__ unsigned long long As2[16][32];
    __shared__ unsigned long long Bs2[16][64];
    int m0 = blockIdx.x * 32, n0 = blockIdx.y * 64;
    int t = threadIdx.x;
    int mi = t >> 4, ni = t & 15;

    unsigned long long acc2[2][4];
    #pragma unroll
    for (int i = 0; i < 2; i++)
        #pragma unroll
        for (int j = 0; j < 4; j++) acc2[i][j] = 0ull;

    for (int kk = 0; kk < SD; kk += 32) {
        {
            int row = t >> 3, q = t & 7;
            float4 v = *(const float4*)(gLN + (size_t)(m0 + row) * SD + kk + q * 4);
            As2[2 * q + 0][row] = pack2(v.x, v.y);
            As2[2 * q + 1][row] = pack2(v.z, v.w);
        }
        #pragma unroll
        for (int rep = 0; rep < 2; rep++) {   // B: 32k x 64n, k-major rows
            int idx = t + rep * 256;
            int k = idx >> 4, q = idx & 15;   // k 0..31, q: 16 float4 per row
            float4 v = *(const float4*)(W1 + (size_t)(kk + k) * (2 * SD) + n0 + q * 4);
            float* bsf = (float*)Bs2;
            int base = ((k >> 1) * 64 + q * 4) * 2 + (k & 1);
            bsf[base + 0] = v.x; bsf[base + 2] = v.y;
            bsf[base + 4] = v.z; bsf[base + 6] = v.w;
        }
        __syncthreads();
        #pragma unroll
        for (int k2 = 0; k2 < 16; k2++) {
            ulonglong2 a2 = *(const ulonglong2*)&As2[k2][mi * 2];
            ulonglong2 b2a = *(const ulonglong2*)&Bs2[k2][ni * 4];
            ulonglong2 b2b = *(const ulonglong2*)&Bs2[k2][ni * 4 + 2];
            ffma2(acc2[0][0], a2.x, b2a.x); ffma2(acc2[0][1], a2.x, b2a.y);
            ffma2(acc2[0][2], a2.x, b2b.x); ffma2(acc2[0][3], a2.x, b2b.y);
            ffma2(acc2[1][0], a2.y, b2a.x); ffma2(acc2[1][1], a2.y, b2a.y);
            ffma2(acc2[1][2], a2.y, b2b.x); ffma2(acc2[1][3], a2.y, b2b.y);
        }
        __syncthreads();
    }
    #pragma unroll
    for (int i = 0; i < 2; i++) {
        int m = m0 + mi * 2 + i;
        #pragma unroll
        for (int j = 0; j < 4; j++) {
            float2 pr = unpack2(acc2[i][j]);
            int n = n0 + ni * 4 + j;
            gHid[(size_t)m * (2 * SD) + n] = fmaxf(pr.x + pr.y + b1[n], 0.f);
        }
    }
}

// ---------------------------------------------------------------------------
// Kernel 7: out += gHid @ W2 (K-split 2, atomic into primed out), f32x2.
// W2 [512][256] k-major. grid (8 m, 4 n, 2 ksplit). Tile 32x64.
// ---------------------------------------------------------------------------
__global__ void __launch_bounds__(256) mlp2_kernel(
    const float* __restrict__ W2, float* __restrict__ out)
{
    __shared__ unsigned long long As2[16][32];
    __shared__ unsigned long long Bs2[16][64];
    int m0 = blockIdx.x * 32, n0 = blockIdx.y * 64;
    int kbase = blockIdx.z * 256;
    int t = threadIdx.x;
    int mi = t >> 4, ni = t & 15;

    unsigned long long acc2[2][4];
    #pragma unroll
    for (int i = 0; i < 2; i++)
        #pragma unroll
        for (int j = 0; j < 4; j++) acc2[i][j] = 0ull;

    for (int kk = kbase; kk < kbase + 256; kk += 32) {
        {
            int row = t >> 3, q = t & 7;
            float4 v = *(const float4*)(gHid + (size_t)(m0 + row) * (2 * SD) + kk + q * 4);
            As2[2 * q + 0][row] = pack2(v.x, v.y);
            As2[2 * q + 1][row] = pack2(v.z, v.w);
        }
        #pragma unroll
        for (int rep = 0; rep < 2; rep++) {
            int idx = t + rep * 256;
            int k = idx >> 4, q = idx & 15;
            float4 v = *(const float4*)(W2 + (size_t)(kk + k) * SD + n0 + q * 4);
            float* bsf = (float*)Bs2;
            int base = ((k >> 1) * 64 + q * 4) * 2 + (k & 1);
            bsf[base + 0] = v.x; bsf[base + 2] = v.y;
            bsf[base + 4] = v.z; bsf[base + 6] = v.w;
        }
        __syncthreads();
        #pragma unroll
        for (int k2 = 0; k2 < 16; k2++) {
            ulonglong2 a2 = *(const ulonglong2*)&As2[k2][mi * 2];
            ulonglong2 b2a = *(const ulonglong2*)&Bs2[k2][ni * 4];
            ulonglong2 b2b = *(const ulonglong2*)&Bs2[k2][ni * 4 + 2];
            ffma2(acc2[0][0], a2.x, b2a.x); ffma2(acc2[0][1], a2.x, b2a.y);
            ffma2(acc2[0][2], a2.x, b2b.x); ffma2(acc2[0][3], a2.x, b2b.y);
            ffma2(acc2[1][0], a2.y, b2a.x); ffma2(acc2[1][1], a2.y, b2a.y);
            ffma2(acc2[1][2], a2.y, b2b.x); ffma2(acc2[1][3], a2.y, b2b.y);
        }
        __syncthreads();
    }
    #pragma unroll
    for (int i = 0; i < 2; i++) {
        int m = m0 + mi * 2 + i;
        #pragma unroll
        for (int j = 0; j < 4; j++) {
            float2 pr = unpack2(acc2[i][j]);
            int n = n0 + ni * 4 + j;
            atomicAdd(&out[(size_t)m * SD + n], pr.x + pr.y);
        }
    }
}

// ---------------------------------------------------------------------------
extern "C" void kernel_launch(void* const* d_in, const int* in_sizes, int n_in,
                              void* d_out, int out_size)
{
    const float* features = (const float*)d_in[0];
    const float* slots    = (const float*)d_in[1];
    const float* Wq   = (const float*)d_in[2];
    const float* bq   = (const float*)d_in[3];
    const float* Wk   = (const float*)d_in[4];
    const float* bk   = (const float*)d_in[5];
    const float* Wv   = (const float*)d_in[6];
    const float* bv   = (const float*)d_in[7];
    const float* W_ih = (const float*)d_in[8];
    const float* b_ih = (const float*)d_in[9];
    const float* W_hh = (const float*)d_in[10];
    const float* b_hh = (const float*)d_in[11];
    const float* g_pre  = (const float*)d_in[12];
    const float* b_pre  = (const float*)d_in[13];
    const float* g_post = (const float*)d_in[14];
    const float* b_post = (const float*)d_in[15];
    const float* W1 = (const float*)d_in[16];
    const float* b1 = (const float*)d_in[17];
    const float* W2 = (const float*)d_in[18];
    const float* b2 = (const float*)d_in[19];
    float* out = (float*)d_out;

    prep_kernel<<<BB * 2, 256>>>(slots, Wq, bq, Wk, bk, g_pre, b_pre);

    size_t smem = (size_t)CC * FST * 4 + (size_t)CC * NJ * 8 + (size_t)NJ * AST * 4;
    cudaFuncSetAttribute(main_kernel, cudaFuncAttributeMaxDynamicSharedMemorySize, (int)smem);
    main_kernel<<<dim3(NPIX / TILE_N, BB), 256, smem>>>(features);

    agg_kernel<<<BB * NH, 256>>>(Wv, bv);
    gru_kernel<<<dim3(NROWS / 32, 12, 2), 256>>>(slots, W_ih, W_hh);
    fin_kernel<<<NROWS / 8, 256>>>(slots, b_ih, b_hh, g_post, b_post, b2, out);
    mlp1_kernel<<<dim3(NROWS / 32, 8), 256>>>(W1, b1);
    mlp2_kernel<<<dim3(NROWS / 32, 4, 2), 256>>>(W2, out);
}

// round 5
// speedup vs baseline: 1.4833x; 1.4833x over previous
#include <cuda_runtime.h>
#include <math.h>

// Problem constants
#define BB 32        // batch
#define CC 128       // FEAT_DIM
#define NPIX 4096    // H*W
#define SD 256       // SLOT_DIM
#define NS 8         // N_SLOTS
#define NH 4         // N_HEADS
#define HD 64        // HEAD_DIM
#define NJ 32        // NH*NS  (j = h*8 + s)
#define TILE_N 128
#define NROWS 256    // BB*NS flattened rows
#define FST 128      // featT smem row stride (XOR-swizzled chunks)
#define AST 132      // attn smem row stride (padded)
#define KT 32
#define RS (NROWS * SD)

// Scratch (device globals; no allocation allowed)
__device__ float gA[BB * CC * NJ];      // per-batch folded K-projection (128x32)
__device__ float gSbias[BB * NJ];       // score bias from bk
__device__ float gM[BB * NJ * CC];      // M[b][j][c]
__device__ float gSsum[BB * NJ];        // sum_n attn[b][j]
__device__ float gAgg[RS];              // agg (GRU input x), [row][dim]
__device__ float gLN[RS];               // post-LN of updated
__device__ float gHid[NROWS * 2 * SD];  // MLP hidden (post-ReLU)
__device__ float gPart[6 * RS];         // gRZ[256][512] | gIN[256][256] | gHN[256][256]

#define gRZ (gPart)
#define gIN (gPart + NROWS * 512)
#define gHN (gPart + NROWS * 512 + NROWS * 256)

// ---------------------------------------------------------------------------
// Kernel 1: LN(slots) -> q(half) -> A fold for a head-pair. grid = BB*2 = 64.
// Also zeros gM, gSsum, and ALL of gPart.
// ---------------------------------------------------------------------------
__global__ void __launch_bounds__(256) prep_kernel(
    const float* __restrict__ slots,
    const float* __restrict__ Wq, const float* __restrict__ bq,
    const float* __restrict__ Wk, const float* __restrict__ bk,
    const float* __restrict__ g_pre, const float* __restrict__ b_pre)
{
    __shared__ float ln_s[NS][SD];
    __shared__ float qp[NS][128];
    __shared__ float q_s[NS][128];
    int b = blockIdx.x >> 1, hp = blockIdx.x & 1;
    int t = threadIdx.x;
    int w = t >> 5, lane = t & 31;

    for (int i = t; i < 16 * CC; i += 256)
        gM[b * NJ * CC + hp * 16 * CC + i] = 0.f;
    if (t < 16) gSsum[b * NJ + hp * 16 + t] = 0.f;
    // zero full gPart: 6*RS = 393216 floats / 64 blocks = 6144 each
    {
        float4* z = (float4*)(gPart + (size_t)blockIdx.x * 6144);
        for (int i = t; i < 1536; i += 256) z[i] = make_float4(0.f, 0.f, 0.f, 0.f);
    }

    {
        const float* row = slots + (size_t)(b * NS + w) * SD;
        float s1 = 0.f, s2 = 0.f;
        for (int k = lane; k < SD; k += 32) { float v = row[k]; s1 += v; s2 += v * v; }
        #pragma unroll
        for (int o = 16; o; o >>= 1) {
            s1 += __shfl_xor_sync(0xffffffffu, s1, o);
            s2 += __shfl_xor_sync(0xffffffffu, s2, o);
        }
        float mu = s1 * (1.f / SD);
        float var = s2 * (1.f / SD) - mu * mu;
        float rs = rsqrtf(var + 1e-5f);
        for (int k = lane; k < SD; k += 32)
            ln_s[w][k] = (row[k] - mu) * rs * g_pre[k] + b_pre[k];
    }
    __syncthreads();

    {
        int dimL = t & 127, ks = t >> 7;
        int dim = hp * 128 + dimL;
        float acc[NS];
        #pragma unroll
        for (int s = 0; s < NS; s++) acc[s] = 0.f;
        int kb = ks * 128;
        #pragma unroll 8
        for (int k = kb; k < kb + 128; k++) {
            float wv = Wq[k * SD + dim];
            #pragma unroll
            for (int s = 0; s < NS; s++) acc[s] += ln_s[s][k] * wv;
        }
        if (ks == 1) {
            #pragma unroll
            for (int s = 0; s < NS; s++) qp[s][dimL] = acc[s];
        }
        __syncthreads();
        if (ks == 0) {
            float bqv = bq[dim];
            #pragma unroll
            for (int s = 0; s < NS; s++) q_s[s][dimL] = acc[s] + qp[s][dimL] + bqv;
        }
    }
    __syncthreads();

    const float scale = 0.125f;
    for (int idx = t; idx < CC * 16; idx += 256) {
        int c = idx >> 4, jl = idx & 15;
        int hl = jl >> 3, s = jl & 7;
        const float* wk = Wk + (size_t)c * SD + (2 * hp + hl) * HD;
        const float* qq = &q_s[s][hl * HD];
        float acc = 0.f;
        #pragma unroll 8
        for (int d = 0; d < HD; d++) acc += wk[d] * qq[d];
        gA[b * CC * NJ + c * NJ + hp * 16 + jl] = acc * scale;
    }
    if (t < 16) {
        int jl = t, hl = jl >> 3, s = jl & 7;
        float acc = 0.f;
        for (int d = 0; d < HD; d++)
            acc += bk[(2 * hp + hl) * HD + d] * q_s[s][hl * HD + d];
        gSbias[b * NJ + hp * 16 + jl] = acc * scale;
    }
}

// ---------------------------------------------------------------------------
// Kernel 2 (heavy): scores + fused softmax + M partials. grid (32, 32).
// featT stored with XOR chunk swizzle: 16B chunk n4 of row c lives at
// chunk (n4 ^ (c & 31)) -> phase-3 strided reads become conflict-free.
// ---------------------------------------------------------------------------
__global__ void __launch_bounds__(256) main_kernel(const float* __restrict__ features)
{
    extern __shared__ float sm[];
    float* featT = sm;                     // [CC][FST] swizzled
    float* A_s   = featT + CC * FST;       // [CC][NJ]
    float* attn  = A_s + CC * NJ;          // [NJ][AST]

    int tile = blockIdx.x, b = blockIdx.y;
    int t = threadIdx.x;
    int n0 = tile * TILE_N;

    const float* fb = features + (size_t)b * CC * NPIX + n0;
    for (int i = t; i < CC * TILE_N / 4; i += 256) {
        int c = i >> 5, n4 = i & 31;
        int sw = (n4 ^ (c & 31)) << 2;
        *(float4*)&featT[c * FST + sw] = ((const float4*)(fb + (size_t)c * NPIX))[n4];
    }
    for (int i = t; i < CC * NJ / 4; i += 256)
        ((float4*)A_s)[i] = ((const float4*)(gA + b * CC * NJ))[i];
    __syncthreads();

    // Phase 1: scores + bias + fused softmax (pair t^1 holds the other 4 slots)
    {
        int jg = t & 7, ng = t >> 3;
        int jb = jg * 4;
        float sbv[4];
        #pragma unroll
        for (int u = 0; u < 4; u++) sbv[u] = gSbias[b * NJ + jb + u];

        float acc[4][4];
        #pragma unroll
        for (int i = 0; i < 4; i++)
            #pragma unroll
            for (int u = 0; u < 4; u++) acc[i][u] = 0.f;
        #pragma unroll 4
        for (int c = 0; c < CC; c++) {
            float4 f = *(const float4*)&featT[c * FST + ((ng ^ (c & 31)) << 2)];
            float4 a = *(const float4*)&A_s[c * NJ + jb];
            float fa[4] = {f.x, f.y, f.z, f.w};
            float aa[4] = {a.x, a.y, a.z, a.w};
            #pragma unroll
            for (int i = 0; i < 4; i++)
                #pragma unroll
                for (int u = 0; u < 4; u++) acc[i][u] += fa[i] * aa[u];
        }
        #pragma unroll
        for (int i = 0; i < 4; i++)
            #pragma unroll
            for (int u = 0; u < 4; u++) acc[i][u] += sbv[u];

        // softmax over 8 slots of a head
        #pragma unroll
        for (int i = 0; i < 4; i++) {
            float m = fmaxf(fmaxf(acc[i][0], acc[i][1]), fmaxf(acc[i][2], acc[i][3]));
            m = fmaxf(m, __shfl_xor_sync(0xffffffffu, m, 1));
            float s = 0.f;
            #pragma unroll
            for (int u = 0; u < 4; u++) { acc[i][u] = __expf(acc[i][u] - m); s += acc[i][u]; }
            s += __shfl_xor_sync(0xffffffffu, s, 1);
            float inv = 1.f / s;
            #pragma unroll
            for (int u = 0; u < 4; u++) acc[i][u] *= inv;
        }

        int nb = ng * 4;
        #pragma unroll
        for (int u = 0; u < 4; u++) {
            float4 v = make_float4(acc[0][u], acc[1][u], acc[2][u], acc[3][u]);
            *(float4*)&attn[(jb + u) * AST + nb] = v;
        }

        float p[4];
        #pragma unroll
        for (int u = 0; u < 4; u++)
            p[u] = acc[0][u] + acc[1][u] + acc[2][u] + acc[3][u];
        #pragma unroll
        for (int u = 0; u < 4; u++) {
            p[u] += __shfl_xor_sync(0xffffffffu, p[u], 8);
            p[u] += __shfl_xor_sync(0xffffffffu, p[u], 16);
        }
        if ((t & 31) < 8) {
            #pragma unroll
            for (int u = 0; u < 4; u++) atomicAdd(&gSsum[b * NJ + jb + u], p[u]);
        }
    }
    __syncthreads();

    // Phase 3: warp owns 4 j rows, lane owns c = {cg, cg+32, cg+64, cg+96}
    {
        int jb = (t >> 5) * 4, cg = t & 31;
        float acc[4][4];   // [u][r]
        #pragma unroll
        for (int u = 0; u < 4; u++)
            #pragma unroll
            for (int r = 0; r < 4; r++) acc[u][r] = 0.f;
        for (int nn = 0; nn < TILE_N; nn += 4) {
            float4 av[4];
            #pragma unroll
            for (int u = 0; u < 4; u++)
                av[u] = *(const float4*)&attn[(jb + u) * AST + nn];   // broadcast
            int swc = ((nn >> 2) ^ cg) << 2;   // swizzled chunk for rows c&31==cg
            #pragma unroll
            for (int r = 0; r < 4; r++) {
                float4 fv = *(const float4*)&featT[(cg + 32 * r) * FST + swc];
                #pragma unroll
                for (int u = 0; u < 4; u++)
                    acc[u][r] += av[u].x * fv.x + av[u].y * fv.y
                               + av[u].z * fv.z + av[u].w * fv.w;
            }
        }
        float* gm = gM + b * NJ * CC;
        #pragma unroll
        for (int u = 0; u < 4; u++)
            #pragma unroll
            for (int r = 0; r < 4; r++)
                atomicAdd(&gm[(jb + u) * CC + cg + 32 * r], acc[u][r]);
    }
}

// ---------------------------------------------------------------------------
// Kernel 3: agg[row][dim] = M[b][j] @ Wv[:,dim] + Ssum*bv. Block per (b, head).
// ---------------------------------------------------------------------------
__global__ void __launch_bounds__(256) agg_kernel(
    const float* __restrict__ Wv, const float* __restrict__ bv)
{
    __shared__ float Ms[NS][CC];
    __shared__ float Wvs[CC][HD];
    int b = blockIdx.x >> 2, h = blockIdx.x & 3;
    int t = threadIdx.x;
    {
        int s = t >> 5, c4 = t & 31;
        ((float4*)&Ms[s][0])[c4] =
            ((const float4*)(gM + (size_t)b * NJ * CC + (h * 8 + s) * CC))[c4];
    }
    #pragma unroll
    for (int j = 0; j < 8; j++) {
        int i = t + j * 256;
        int c = i >> 4, d4 = i & 15;
        ((float4*)&Wvs[c][0])[d4] =
            ((const float4*)(Wv + (size_t)c * SD + h * HD))[d4];
    }
    __syncthreads();
    #pragma unroll
    for (int rep = 0; rep < 2; rep++) {
        int o = t + rep * 256;
        int s = o >> 6, d = o & 63;
        int j = h * 8 + s;
        float acc = gSsum[b * NJ + j] * bv[h * HD + d];
        #pragma unroll 8
        for (int c = 0; c < CC; c++) acc += Ms[s][c] * Wvs[c][d];
        gAgg[(size_t)(b * NS + s) * SD + h * HD + d] = acc;
    }
}

// ---------------------------------------------------------------------------
// Kernel 4: GRU gate GEMM. Tile 64m x 32d x 3 gates, K-split 2, phase-split 2.
// grid (4 m-tiles, 8 d-tiles, 4=phase*2+khalf) = 128 blocks.
// Thread tile 4m x 2d x 3g = 24 MACs per 10 scalar LDS.
// Outputs atomically accumulate into zero-primed gPart sections.
// ---------------------------------------------------------------------------
__global__ void __launch_bounds__(256) gru_kernel(
    const float* __restrict__ slots,
    const float* __restrict__ W_ih, const float* __restrict__ W_hh)
{
    __shared__ float As[64][KT + 1];        // [m][k]
    __shared__ float Bs[3][32][KT + 1];     // [gate][d][k]
    int m0 = blockIdx.x * 64, dim0 = blockIdx.y * 32;
    int phase = blockIdx.z >> 1, kh = blockIdx.z & 1;
    int t = threadIdx.x;
    int di = t & 15, mi = t >> 4;           // thread: m = 4mi+ii, d = 2di+jj

    float accg[3][4][2];
    #pragma unroll
    for (int g = 0; g < 3; g++)
        #pragma unroll
        for (int i = 0; i < 4; i++)
            #pragma unroll
            for (int j = 0; j < 2; j++) accg[g][i][j] = 0.f;

    int lk = t & 7;
    const float* Ag = phase ? slots : gAgg;
    const float* Wg = phase ? W_hh : W_ih;
    int kbase = kh * 128;

    for (int k0 = kbase; k0 < kbase + 128; k0 += KT) {
        // stage A slab: 64 rows x 32 k (2 reps of scalar-scatter from float4)
        #pragma unroll
        for (int rep = 0; rep < 2; rep++) {
            int idx = t + rep * 256;
            int row = idx >> 3;
            float4 v = *(const float4*)(Ag + (size_t)(m0 + row) * SD + k0 + lk * 4);
            As[row][lk * 4 + 0] = v.x; As[row][lk * 4 + 1] = v.y;
            As[row][lk * 4 + 2] = v.z; As[row][lk * 4 + 3] = v.w;
        }
        // stage B slabs: 3 gates x 32 dims x 32 k
        {
            int lm = t >> 3;
            #pragma unroll
            for (int g = 0; g < 3; g++) {
                float4 v = *(const float4*)(Wg + (size_t)(g * SD + dim0 + lm) * SD + k0 + lk * 4);
                Bs[g][lm][lk * 4 + 0] = v.x; Bs[g][lm][lk * 4 + 1] = v.y;
                Bs[g][lm][lk * 4 + 2] = v.z; Bs[g][lm][lk * 4 + 3] = v.w;
            }
        }
        __syncthreads();
        #pragma unroll 4
        for (int k = 0; k < KT; k++) {
            float a[4];
            #pragma unroll
            for (int i = 0; i < 4; i++) a[i] = As[mi * 4 + i][k];
            #pragma unroll
            for (int g = 0; g < 3; g++) {
                float b0 = Bs[g][di * 2 + 0][k];
                float b1 = Bs[g][di * 2 + 1][k];
                #pragma unroll
                for (int i = 0; i < 4; i++) {
                    accg[g][i][0] += a[i] * b0;
                    accg[g][i][1] += a[i] * b1;
                }
            }
        }
        __syncthreads();
    }

    float* dstN = phase ? gHN : gIN;
    #pragma unroll
    for (int i = 0; i < 4; i++) {
        int m = m0 + mi * 4 + i;
        #pragma unroll
        for (int j = 0; j < 2; j++) {
            int d = dim0 + di * 2 + j;
            atomicAdd(&gRZ[(size_t)m * 512 + d], accg[0][i][j]);
            atomicAdd(&gRZ[(size_t)m * 512 + 256 + d], accg[1][i][j]);
            atomicAdd(&dstN[(size_t)m * SD + d], accg[2][i][j]);
        }
    }
}

// ---------------------------------------------------------------------------
// Kernel 5: GRU nonlin + post-LN + prime out = upd + b2. grid 32, warp/row.
// ---------------------------------------------------------------------------
__global__ void __launch_bounds__(256) fin_kernel(
    const float* __restrict__ slots,
    const float* __restrict__ b_ih, const float* __restrict__ b_hh,
    const float* __restrict__ g_post, const float* __restrict__ b_post,
    const float* __restrict__ b2, float* __restrict__ out)
{
    int row = blockIdx.x * 8 + (threadIdx.x >> 5);
    int lane = threadIdx.x & 31;
    float vals[8];
    float s1 = 0.f, s2 = 0.f;
    size_t ro = (size_t)row * SD;
    #pragma unroll
    for (int r8 = 0; r8 < 8; r8++) {
        int d = r8 * 32 + lane;
        float rz_r = gRZ[(size_t)row * 512 + d] + b_ih[d] + b_hh[d];
        float rz_z = gRZ[(size_t)row * 512 + 256 + d] + b_ih[SD + d] + b_hh[SD + d];
        float in_ = gIN[ro + d] + b_ih[2 * SD + d];
        float hn = gHN[ro + d] + b_hh[2 * SD + d];
        float r = 1.f / (1.f + expf(-rz_r));
        float z = 1.f / (1.f + expf(-rz_z));
        float nn = tanhf(in_ + r * hn);
        float hp = slots[ro + d];
        float v = (1.f - z) * nn + z * hp;
        out[ro + d] = v + b2[d];
        vals[r8] = v;
        s1 += v; s2 += v * v;
    }
    #pragma unroll
    for (int o = 16; o; o >>= 1) {
        s1 += __shfl_xor_sync(0xffffffffu, s1, o);
        s2 += __shfl_xor_sync(0xffffffffu, s2, o);
    }
    float mu = s1 * (1.f / SD);
    float var = s2 * (1.f / SD) - mu * mu;
    float rs = rsqrtf(var + 1e-5f);
    #pragma unroll
    for (int r8 = 0; r8 < 8; r8++) {
        int d = r8 * 32 + lane;
        gLN[ro + d] = (vals[r8] - mu) * rs * g_post[d] + b_post[d];
    }
}

// ---------------------------------------------------------------------------
// Kernel 6: gHid = relu(gLN @ W1 + b1). Grid (8, 8), tile 32x64.
// ---------------------------------------------------------------------------
__global__ void __launch_bounds__(256) mlp1_kernel(
    const float* __restrict__ W1, const float* __restrict__ b1)
{
    __shared__ float As[32][KT + 1];
    __shared__ float Bs[KT][68];
    int m0 = blockIdx.x * 32, n0 = blockIdx.y * 64;
    int t = threadIdx.x;
    int ni = t & 15, mi = t >> 4;
    float acc[2][4] = {{0,0,0,0},{0,0,0,0}};
    int lm = t >> 3, lk = t & 7;

    for (int k0 = 0; k0 < SD; k0 += KT) {
        {
            float4 v = *(const float4*)(gLN + (size_t)(m0 + lm) * SD + k0 + lk * 4);
            As[lm][lk * 4 + 0] = v.x; As[lm][lk * 4 + 1] = v.y;
            As[lm][lk * 4 + 2] = v.z; As[lm][lk * 4 + 3] = v.w;
        }
        #pragma unroll
        for (int rep = 0; rep < 2; rep++) {
            int i = t + rep * 256;
            int k = i >> 4, nc = i & 15;
            float4 v = *(const float4*)(W1 + (size_t)(k0 + k) * (2 * SD) + n0 + nc * 4);
            *(float4*)&Bs[k][nc * 4] = v;
        }
        __syncthreads();
        #pragma unroll 8
        for (int k = 0; k < KT; k++) {
            float a0 = As[mi * 2 + 0][k], a1 = As[mi * 2 + 1][k];
            float4 bv4 = *(const float4*)&Bs[k][ni * 4];
            acc[0][0] += a0 * bv4.x; acc[0][1] += a0 * bv4.y;
            acc[0][2] += a0 * bv4.z; acc[0][3] += a0 * bv4.w;
            acc[1][0] += a1 * bv4.x; acc[1][1] += a1 * bv4.y;
            acc[1][2] += a1 * bv4.z; acc[1][3] += a1 * bv4.w;
        }
        __syncthreads();
    }
    #pragma unroll
    for (int ii = 0; ii < 2; ii++) {
        int m = m0 + mi * 2 + ii;
        #pragma unroll
        for (int u = 0; u < 4; u++) {
            int n = n0 + ni * 4 + u;
            gHid[(size_t)m * (2 * SD) + n] = fmaxf(acc[ii][u] + b1[n], 0.f);
        }
    }
}

// ---------------------------------------------------------------------------
// Kernel 7: out += gHid @ W2, K-split 2 (atomic into primed out).
// Grid (16, 4, 2), tile 16m x 64n x K256.
// ---------------------------------------------------------------------------
__global__ void __launch_bounds__(256) mlp2_kernel(
    const float* __restrict__ W2, float* __restrict__ out)
{
    __shared__ float As[16][KT + 1];
    __shared__ float Bs[KT][68];
    int m0 = blockIdx.x * 16, n0 = blockIdx.y * 64;
    int kbase = blockIdx.z * 256;
    int t = threadIdx.x;
    int ni = t & 15, mi = t >> 4;
    float acc[4] = {0, 0, 0, 0};

    for (int k0 = kbase; k0 < kbase + 256; k0 += KT) {
        if (t < 128) {
            int lm = t >> 3, lk = t & 7;
            float4 v = *(const float4*)(gHid + (size_t)(m0 + lm) * (2 * SD) + k0 + lk * 4);
            As[lm][lk * 4 + 0] = v.x; As[lm][lk * 4 + 1] = v.y;
            As[lm][lk * 4 + 2] = v.z; As[lm][lk * 4 + 3] = v.w;
        }
        #pragma unroll
        for (int rep = 0; rep < 2; rep++) {
            int i = t + rep * 256;
            int k = i >> 4, nc = i & 15;
            float4 v = *(const float4*)(W2 + (size_t)(k0 + k) * SD + n0 + nc * 4);
            *(float4*)&Bs[k][nc * 4] = v;
        }
        __syncthreads();
        #pragma unroll 8
        for (int k = 0; k < KT; k++) {
            float a = As[mi][k];
            float4 bv4 = *(const float4*)&Bs[k][ni * 4];
            acc[0] += a * bv4.x; acc[1] += a * bv4.y;
            acc[2] += a * bv4.z; acc[3] += a * bv4.w;
        }
        __syncthreads();
    }
    int m = m0 + mi;
    #pragma unroll
    for (int u = 0; u < 4; u++) {
        int n = n0 + ni * 4 + u;
        atomicAdd(&out[(size_t)m * SD + n], acc[u]);
    }
}

// ---------------------------------------------------------------------------
extern "C" void kernel_launch(void* const* d_in, const int* in_sizes, int n_in,
                              void* d_out, int out_size)
{
    const float* features = (const float*)d_in[0];
    const float* slots    = (const float*)d_in[1];
    const float* Wq   = (const float*)d_in[2];
    const float* bq   = (const float*)d_in[3];
    const float* Wk   = (const float*)d_in[4];
    const float* bk   = (const float*)d_in[5];
    const float* Wv   = (const float*)d_in[6];
    const float* bv   = (const float*)d_in[7];
    const float* W_ih = (const float*)d_in[8];
    const float* b_ih = (const float*)d_in[9];
    const float* W_hh = (const float*)d_in[10];
    const float* b_hh = (const float*)d_in[11];
    const float* g_pre  = (const float*)d_in[12];
    const float* b_pre  = (const float*)d_in[13];
    const float* g_post = (const float*)d_in[14];
    const float* b_post = (const float*)d_in[15];
    const float* W1 = (const float*)d_in[16];
    const float* b1 = (const float*)d_in[17];
    const float* W2 = (const float*)d_in[18];
    const float* b2 = (const float*)d_in[19];
    float* out = (float*)d_out;

    prep_kernel<<<BB * 2, 256>>>(slots, Wq, bq, Wk, bk, g_pre, b_pre);

    size_t smem = (size_t)(CC * FST + CC * NJ + NJ * AST) * sizeof(float);
    cudaFuncSetAttribute(main_kernel, cudaFuncAttributeMaxDynamicSharedMemorySize, (int)smem);
    main_kernel<<<dim3(NPIX / TILE_N, BB), 256, smem>>>(features);

    agg_kernel<<<BB * NH, 256>>>(Wv, bv);
    gru_kernel<<<dim3(NROWS / 64, SD / 32, 4), 256>>>(slots, W_ih, W_hh);
    fin_kernel<<<NROWS / 8, 256>>>(slots, b_ih, b_hh, g_post, b_post, b2, out);
    mlp1_kernel<<<dim3(NROWS / 32, (2 * SD) / 64), 256>>>(W1, b1);
    mlp2_kernel<<<dim3(NROWS / 16, SD / 64, 2), 256>>>(W2, out);
}